// round 16
// baseline (speedup 1.0000x reference)
#include <cuda_runtime.h>
#include <cuda_fp16.h>

#define Bb 64
#define Tt 512
#define Ii 1024
#define Hh 1024
#define G3 3072
#define NCTA 128
#define WSTRH 1032   // W smem row stride (halfs): 2064B == 16 mod 128, 16B-aligned

// ---------------- scratch (static device globals; no allocation) ----------------
static __device__ float  g_h[2][Bb * Hh];              // fp32 h (init + final only)
static __device__ __half g_hh[2][Bb * Hh];             // fp16 ping-pong hidden state
static __device__ __half g_inh[(size_t)Bb * Tt * Ii];  // fp16 input mirror
static __device__ float  g_dm[Tt * Bb];                // [t][b] mask: done?0:1
static __device__ int    g_kind;                       // 1 = done is 1-byte, 0 = 4-byte
static __device__ unsigned g_bar;                      // grid barrier counter

// ---------------- mma helpers ----------------
// fp16 m16n8k16: A 4 regs (2 f16 each), B 2 regs, C 4 f32
// C: c0=(gid,tig*2) c1=(gid,tig*2+1) c2=(gid+8,tig*2) c3=(gid+8,tig*2+1)
__device__ __forceinline__ void mma16(float* c, const unsigned* a, const unsigned* b) {
    asm("mma.sync.aligned.m16n8k16.row.col.f32.f16.f16.f32 "
        "{%0,%1,%2,%3}, {%4,%5,%6,%7}, {%8,%9}, {%0,%1,%2,%3};"
        : "+f"(c[0]), "+f"(c[1]), "+f"(c[2]), "+f"(c[3])
        : "r"(a[0]), "r"(a[1]), "r"(a[2]), "r"(a[3]), "r"(b[0]), "r"(b[1]));
}
#define LDSM4(r, addr)                                                            \
    asm volatile("ldmatrix.sync.aligned.m8n8.x4.shared.b16 {%0,%1,%2,%3}, [%4];"  \
                 : "=r"((r)[0]), "=r"((r)[1]), "=r"((r)[2]), "=r"((r)[3])         \
                 : "r"(addr))

// ---------------- done-dtype detection (graph-safe, device-side) ----------------
__global__ void detect_kernel(const unsigned* __restrict__ w) {
    __shared__ int hif, f32f;
    if (threadIdx.x == 0) { hif = 0; f32f = 0; }
    __syncthreads();
    for (int i = threadIdx.x; i < 8192; i += blockDim.x) {
        unsigned v = w[i];
        if (v == 0x3F800000u) atomicOr(&f32f, 1);
        else if (v & 0xFFFFFF00u) atomicOr(&hif, 1);
    }
    __syncthreads();
    if (threadIdx.x == 0) g_kind = (!f32f && hif) ? 1 : 0;
}

__global__ void prep_kernel(const void* __restrict__ done, const float* __restrict__ hidden) {
    int i = blockIdx.x * blockDim.x + threadIdx.x;
    if (i == 0) g_bar = 0u;
    if (i < Tt * Bb) {
        int t = i / Bb, b = i - t * Bb;
        int src = b * Tt + t;   // done is [B,T]
        bool d;
        if (g_kind == 1) d = ((const unsigned char*)done)[src] != 0;
        else             d = ((const unsigned*)done)[src] != 0u;
        g_dm[i] = d ? 0.f : 1.f;
    }
    if (i < Bb * Hh) {
        float hv = hidden[i];
        g_h[0][i] = hv;
        g_hh[0][i] = __float2half_rn(hv);
    }
}

// fp32 input -> fp16 mirror (8 elements/thread)
__global__ void cvt_kernel(const float* __restrict__ src, int n8) {
    int i = blockIdx.x * blockDim.x + threadIdx.x;
    if (i >= n8) return;
    size_t off = (size_t)i * 8;
    float4 v0 = *(const float4*)(src + off);
    float4 v1 = *(const float4*)(src + off + 4);
    __half2 h[4] = { __floats2half2_rn(v0.x, v0.y), __floats2half2_rn(v0.z, v0.w),
                     __floats2half2_rn(v1.x, v1.y), __floats2half2_rn(v1.z, v1.w) };
    *(uint4*)(g_inh + off) = *(uint4*)h;
}

// ---------------- fused persistent kernel: gi-GEMM + all 512 GRU steps ----------------
// 128 CTAs x 8 h-cols, 8 warps, K-split (warps 0-3: K[0,512), 4-7: K[512,1024)).
// Both W_hh and W_ih 24-row slices resident in smem (fp16). Per step t the
// sync-free mainloop streams BOTH h_t (recurrent GEMM, gates) and x_{t+1}
// (input GEMM -> gi for the NEXT step, kept in registers; no gi buffer, no
// separate gemm1 kernel). t = -1 iteration bootstraps gi_0 (x-only).
// fp32 accumulate + fp32 gate math; release/acquire grid barrier per step.
__global__ void __launch_bounds__(256, 1) rec_kernel(
    const float* __restrict__ Whh, const float* __restrict__ Wih,
    const float* __restrict__ bhh, const float* __restrict__ bih,
    float* __restrict__ outp)
{
    extern __shared__ __half dynh[];
    __half* wsh = dynh;                          // W_hh: 24 * WSTRH halfs
    __half* wsi = dynh + 24 * WSTRH;             // W_ih: 24 * WSTRH halfs
    __half* hsu = wsi + 24 * WSTRH;              // h rings: 8 warps x 4 stages x 640 halfs
    __half* xsu = hsu + 8 * 2560;                // x rings: same shape
    __shared__ float red[128 * 25];              // K-split partials (gates 12 + gi 12)
    __shared__ float bshh[24], bshi[24];

    const int tid = threadIdx.x;
    const int lane = tid & 31, wid = tid >> 5;
    const int gid = lane >> 2, tig = lane & 3;
    const int ks = wid >> 2;                     // K-split group 0/1
    const int mrow0 = (wid & 3) * 16;            // warp's 16 M-rows
    const int col0 = blockIdx.x * 8;
    const int b0r = mrow0 + gid;
    __half* hw = hsu + wid * 2560;
    __half* xw = xsu + wid * 2560;
    const unsigned hw_u32 = (unsigned)__cvta_generic_to_shared(hw);
    const unsigned xw_u32 = (unsigned)__cvta_generic_to_shared(xw);
    const unsigned wsh_u32 = (unsigned)__cvta_generic_to_shared(wsh);
    const unsigned wsi_u32 = (unsigned)__cvta_generic_to_shared(wsi);

    // Load both W slices once (fp16): row r = (gate r/8, col col0 + r%8), K=1024.
    for (int f = tid; f < 24 * 256; f += 256) {
        int r = f >> 8, cq = f & 255;
        size_t goff = (size_t)((r >> 3) * Hh + col0 + (r & 7)) * Hh + cq * 4;
        float4 vh = *(const float4*)&Whh[goff];
        float4 vi = *(const float4*)&Wih[goff];
        *(__half2*)&wsh[r * WSTRH + cq * 4]     = __floats2half2_rn(vh.x, vh.y);
        *(__half2*)&wsh[r * WSTRH + cq * 4 + 2] = __floats2half2_rn(vh.z, vh.w);
        *(__half2*)&wsi[r * WSTRH + cq * 4]     = __floats2half2_rn(vi.x, vi.y);
        *(__half2*)&wsi[r * WSTRH + cq * 4 + 2] = __floats2half2_rn(vi.z, vi.w);
    }
    if (tid < 24) {
        bshh[tid] = bhh[(tid >> 3) * Hh + col0 + (tid & 7)];
        bshi[tid] = bih[(tid >> 3) * Hh + col0 + (tid & 7)];
    }

    // ldmatrix per-lane addressing (validated fp16 layouts)
    const int arow = (lane < 16) ? lane : (lane - 16);
    const int akoff = (lane >= 16) ? 8 : 0;
    const unsigned ah_addr0 = hw_u32 + ((unsigned)(arow * 40 + akoff) << 1);
    const unsigned ax_addr0 = xw_u32 + ((unsigned)(arow * 40 + akoff) << 1);
    const int b_nrow = lane & 7, b_k8 = (lane >> 3) * 8;
    unsigned bh_addr[3], bi_addr[3];
    #pragma unroll
    for (int g = 0; g < 3; g++) {
        unsigned off = ((unsigned)((g * 8 + b_nrow) * WSTRH + b_k8) << 1);
        bh_addr[g] = wsh_u32 + off;
        bi_addr[g] = wsi_u32 + off;
    }

    float hloc[4] = {0.f, 0.f, 0.f, 0.f};
    if (wid < 4) {
        int cb = col0 + tig * 2;
        hloc[0] = g_h[0][b0r * Hh + cb];
        hloc[1] = g_h[0][b0r * Hh + cb + 1];
        hloc[2] = g_h[0][(b0r + 8) * Hh + cb];
        hloc[3] = g_h[0][(b0r + 8) * Hh + cb + 1];
    }
    __syncthreads();

    const int kbase = ks * 512;                  // warp group's K offset (halfs)
    const int rrow = (tid & 127) * 25;           // shared red row (writer==reader row)

    float gpre[12];                              // gi for current step (fragment layout)
    float mb0 = 0.f, mb1 = 0.f;
    if (wid < 4) {                               // mask for t=0
        mb0 = __ldg(&g_dm[b0r]);
        mb1 = __ldg(&g_dm[b0r + 8]);
    }

// issue h(ch) + x(ch) slabs; one commit group covers both
#define ISSUE_CHUNK(ch) do {                                                     \
        unsigned _stg = (unsigned)(((ch) & 3) * 1280);                           \
        _Pragma("unroll")                                                        \
        for (int _j = 0; _j < 2; _j++) {                                         \
            int _idx = _j * 32 + lane, _row = _idx >> 2, _seg = _idx & 3;        \
            unsigned _off = _stg + (unsigned)(_row * 80 + _seg * 16);            \
            const __half* _sh = hh_in + (mrow0 + _row) * Hh + kbase + (ch) * 32 + _seg * 8; \
            const __half* _sx = xin + (size_t)(mrow0 + _row) * (Tt * Ii) + kbase + (ch) * 32 + _seg * 8; \
            asm volatile("cp.async.cg.shared.global [%0], [%1], 16;"             \
                         :: "r"(hw_u32 + _off), "l"(_sh));                       \
            asm volatile("cp.async.cg.shared.global [%0], [%1], 16;"             \
                         :: "r"(xw_u32 + _off), "l"(_sx));                       \
        }                                                                        \
        asm volatile("cp.async.commit_group;");                                  \
    } while (0)

    for (int t = -1; t < Tt; ++t) {
        const __half* __restrict__ hh_in  = g_hh[(t < 0 ? 0 : t) & 1];
        __half* __restrict__       hh_out = g_hh[(t + 1) & 1];
        int tn = (t + 1 < Tt) ? (t + 1) : (Tt - 1);        // x timestep (clamped)
        const __half* __restrict__ xin = g_inh + (size_t)tn * Ii;

        ISSUE_CHUNK(0); ISSUE_CHUNK(1); ISSUE_CHUNK(2);

        float c[3][4], cx[3][4];
        #pragma unroll
        for (int g = 0; g < 3; g++)
            #pragma unroll
            for (int s = 0; s < 4; s++) { c[g][s] = 0.f; cx[g][s] = 0.f; }

        #pragma unroll 1
        for (int i = 0; i < 16; ++i) {
            if (i < 14)       asm volatile("cp.async.wait_group 2;");
            else if (i == 14) asm volatile("cp.async.wait_group 1;");
            else              asm volatile("cp.async.wait_group 0;");
            if (i + 3 < 16) ISSUE_CHUNK(i + 3);

            const int kb = kbase + i * 32;       // halfs
            unsigned bfh[3][4], bfi[3][4];
            #pragma unroll
            for (int g = 0; g < 3; g++) {
                LDSM4(bfh[g], bh_addr[g] + ((unsigned)kb << 1));
                LDSM4(bfi[g], bi_addr[g] + ((unsigned)kb << 1));
            }
            const unsigned stg = (unsigned)((i & 3) * 1280);
            #pragma unroll
            for (int s = 0; s < 2; s++) {
                unsigned ah[4], ax[4];
                LDSM4(ah, ah_addr0 + stg + (unsigned)(s * 32));
                LDSM4(ax, ax_addr0 + stg + (unsigned)(s * 32));
                #pragma unroll
                for (int g = 0; g < 3; g++) {
                    mma16(c[g],  ah, &bfh[g][s * 2]);
                    mma16(cx[g], ax, &bfi[g][s * 2]);
                }
            }
        }

        // K-split reduction: warps 4-7 park gates + gi partials, one sync.
        if (wid >= 4) {
            #pragma unroll
            for (int g = 0; g < 3; g++)
                #pragma unroll
                for (int s = 0; s < 4; s++) {
                    red[rrow + g * 4 + s]      = c[g][s];
                    red[rrow + 12 + g * 4 + s] = cx[g][s];
                }
        }
        __syncthreads();

        if (wid < 4) {
            int cb = col0 + tig * 2;
            if (t >= 0) {
                float hn[4];
                #pragma unroll
                for (int s = 0; s < 4; s++) {
                    int r = s >> 1, i = s & 1;
                    int cc = tig * 2 + i;
                    float mb = r ? mb1 : mb0;
                    float gr = (c[0][s] + red[rrow + s])     * mb + bshh[cc];
                    float gz = (c[1][s] + red[rrow + 4 + s]) * mb + bshh[8 + cc];
                    float gn = (c[2][s] + red[rrow + 8 + s]) * mb + bshh[16 + cc];
                    float rg = __fdividef(1.f, 1.f + __expf(-(gpre[r * 6 + i] + gr)));
                    float zg = __fdividef(1.f, 1.f + __expf(-(gpre[r * 6 + 2 + i] + gz)));
                    float xa = gpre[r * 6 + 4 + i] + rg * gn;
                    float ng = 1.f - __fdividef(2.f, __expf(2.f * xa) + 1.f);
                    float hm = hloc[s] * mb;
                    hn[s] = (1.f - zg) * ng + zg * hm;
                    hloc[s] = hn[s];
                }
                __half2 p01 = __floats2half2_rn(hn[0], hn[1]);
                __half2 p23 = __floats2half2_rn(hn[2], hn[3]);
                __stcg((unsigned*)&hh_out[b0r * Hh + cb],       *(unsigned*)&p01);
                __stcg((unsigned*)&hh_out[(b0r + 8) * Hh + cb], *(unsigned*)&p23);
                __stcs((float2*)&outp[((size_t)b0r * Tt + t) * Hh + cb],       make_float2(hn[0], hn[1]));
                __stcs((float2*)&outp[((size_t)(b0r + 8) * Tt + t) * Hh + cb], make_float2(hn[2], hn[3]));
                if (t == Tt - 1) {
                    *(float2*)&g_h[0][b0r * Hh + cb]       = make_float2(hn[0], hn[1]);
                    *(float2*)&g_h[0][(b0r + 8) * Hh + cb] = make_float2(hn[2], hn[3]);
                }
            }
            // gi for next step: cx + partner partials + b_ih (NOT masked)
            #pragma unroll
            for (int g = 0; g < 3; g++)
                #pragma unroll
                for (int s = 0; s < 4; s++) {
                    int r = s >> 1, i = s & 1;
                    gpre[r * 6 + g * 2 + i] =
                        cx[g][s] + red[rrow + 12 + g * 4 + s] + bshi[g * 8 + tig * 2 + i];
                }
            // done-mask for next step
            if (t + 1 < Tt) {
                mb0 = __ldg(&g_dm[(t + 1) * Bb + b0r]);
                mb1 = __ldg(&g_dm[(t + 1) * Bb + b0r + 8]);
            }
        }

        // grid barrier (only for real steps): release/acquire h_out hand-off.
        if (t >= 0) {
            __syncthreads();
            if (tid == 0) {
                unsigned target = (unsigned)(t + 1) * (unsigned)gridDim.x;
                unsigned one = 1u, v;
                asm volatile("red.release.gpu.global.add.u32 [%0], %1;"
                             :: "l"(&g_bar), "r"(one) : "memory");
                do {
                    asm volatile("ld.acquire.gpu.global.u32 %0, [%1];"
                                 : "=r"(v) : "l"(&g_bar) : "memory");
                } while (v < target);
            }
            __syncthreads();
        } else {
            __syncthreads();   // red reuse safety before next iteration
        }
    }
#undef ISSUE_CHUNK
}

__global__ void tail_kernel(float* __restrict__ dst) {
    int i = blockIdx.x * blockDim.x + threadIdx.x;
    if (i < Bb * Hh) dst[i] = g_h[0][i];   // final h written by rec at t=511
}

extern "C" void kernel_launch(void* const* d_in, const int* in_sizes, int n_in,
                              void* d_out, int out_size) {
    const float* input  = (const float*)d_in[0];
    const float* hidden = (const float*)d_in[1];
    const void*  done   = d_in[2];
    const float* W_ih   = (const float*)d_in[3];
    const float* W_hh   = (const float*)d_in[4];
    const float* b_ih   = (const float*)d_in[5];
    const float* b_hh   = (const float*)d_in[6];
    float* out = (float*)d_out;

    const int rec_smem = (2 * 24 * WSTRH + 2 * 8 * 2560) * 2;  // 180992 B

    cudaFuncSetAttribute(rec_kernel, cudaFuncAttributeMaxDynamicSharedMemorySize, rec_smem);

    detect_kernel<<<1, 256>>>((const unsigned*)done);
    prep_kernel<<<256, 256>>>(done, hidden);
    {
        int n8i = (Bb * Tt * Ii) / 8;   // 4194304
        cvt_kernel<<<(n8i + 255) / 256, 256>>>(input, n8i);
    }
    rec_kernel<<<NCTA, 256, rec_smem>>>(W_hh, W_ih, b_hh, b_ih, out);
    if (out_size >= Bb * Tt * Hh + Bb * Hh)
        tail_kernel<<<64, 1024>>>(out + (size_t)Bb * Tt * Hh);
}

// round 17
// speedup vs baseline: 1.6066x; 1.6066x over previous
#include <cuda_runtime.h>
#include <cuda_fp16.h>

#define Bb 64
#define Tt 512
#define Ii 1024
#define Hh 1024
#define G3 3072
#define NCTA 128
#define WSTRH 1032   // W smem row stride (halfs): 2064B == 16 mod 128, 16B-aligned
#define HROW 520     // h slab row stride (halfs): 1040B == 16 mod 128, 16B-aligned

// ---------------- scratch (static device globals; no allocation) ----------------
static __device__ float  g_gi[(size_t)Tt * Bb * G3];   // [t][b][3H], b_ih folded in
static __device__ float  g_h[2][Bb * Hh];              // fp32 h (init + final only)
static __device__ __half g_hh[2][Bb * Hh];             // fp16 ping-pong hidden state
static __device__ __half g_inh[(size_t)Bb * Tt * Ii];  // fp16 input mirror
static __device__ __half g_wih[G3 * Ii];               // fp16 W_ih mirror
static __device__ float  g_dm[Tt * Bb];                // [t][b] mask: done?0:1
static __device__ int    g_kind;                       // 1 = done is 1-byte, 0 = 4-byte
static __device__ unsigned g_bar;                      // grid barrier counter

// ---------------- mma helpers ----------------
// fp16 m16n8k16: A 4 regs (2 f16 each), B 2 regs, C 4 f32
// C: c0=(gid,tig*2) c1=(gid,tig*2+1) c2=(gid+8,tig*2) c3=(gid+8,tig*2+1)
__device__ __forceinline__ void mma16(float* c, const unsigned* a, const unsigned* b) {
    asm("mma.sync.aligned.m16n8k16.row.col.f32.f16.f16.f32 "
        "{%0,%1,%2,%3}, {%4,%5,%6,%7}, {%8,%9}, {%0,%1,%2,%3};"
        : "+f"(c[0]), "+f"(c[1]), "+f"(c[2]), "+f"(c[3])
        : "r"(a[0]), "r"(a[1]), "r"(a[2]), "r"(a[3]), "r"(b[0]), "r"(b[1]));
}
#define LDSM4(r, addr)                                                            \
    asm volatile("ldmatrix.sync.aligned.m8n8.x4.shared.b16 {%0,%1,%2,%3}, [%4];"  \
                 : "=r"((r)[0]), "=r"((r)[1]), "=r"((r)[2]), "=r"((r)[3])         \
                 : "r"(addr))

// ---------------- done-dtype detection (graph-safe, device-side) ----------------
__global__ void detect_kernel(const unsigned* __restrict__ w) {
    __shared__ int hif, f32f;
    if (threadIdx.x == 0) { hif = 0; f32f = 0; }
    __syncthreads();
    for (int i = threadIdx.x; i < 8192; i += blockDim.x) {
        unsigned v = w[i];
        if (v == 0x3F800000u) atomicOr(&f32f, 1);
        else if (v & 0xFFFFFF00u) atomicOr(&hif, 1);
    }
    __syncthreads();
    if (threadIdx.x == 0) g_kind = (!f32f && hif) ? 1 : 0;
}

__global__ void prep_kernel(const void* __restrict__ done, const float* __restrict__ hidden) {
    int i = blockIdx.x * blockDim.x + threadIdx.x;
    if (i == 0) g_bar = 0u;
    if (i < Tt * Bb) {
        int t = i / Bb, b = i - t * Bb;
        int src = b * Tt + t;   // done is [B,T]
        bool d;
        if (g_kind == 1) d = ((const unsigned char*)done)[src] != 0;
        else             d = ((const unsigned*)done)[src] != 0u;
        g_dm[i] = d ? 0.f : 1.f;
    }
    if (i < Bb * Hh) {
        float hv = hidden[i];
        g_h[0][i] = hv;
        g_hh[0][i] = __float2half_rn(hv);
    }
}

// fp32 -> fp16 mirror (8 elements/thread); which: 0 = input->g_inh, 1 = W_ih->g_wih
__global__ void cvt_kernel(const float* __restrict__ src, int n8, int which) {
    int i = blockIdx.x * blockDim.x + threadIdx.x;
    if (i >= n8) return;
    size_t off = (size_t)i * 8;
    float4 v0 = *(const float4*)(src + off);
    float4 v1 = *(const float4*)(src + off + 4);
    __half2 h[4] = { __floats2half2_rn(v0.x, v0.y), __floats2half2_rn(v0.z, v0.w),
                     __floats2half2_rn(v1.x, v1.y), __floats2half2_rn(v1.z, v1.w) };
    __half* dst = which ? g_wih : g_inh;
    *(uint4*)(dst + off) = *(uint4*)h;
}

// ---------------- GEMM1 (fp16): gi[t][b][:] = input[b][t][:] @ W_ih^T + b_ih ----------------
// M=32768 (m=b*512+t), N=3072, K=1024. CTA 128x128x32, 8 warps (2x4), 4-stage
// cp.async pipeline, ldmatrix frags, m16n8k16 HMMA with fp32 accumulate.
__global__ void __launch_bounds__(256) gemm1_kernel(
    const __half* __restrict__ A, const __half* __restrict__ W,
    const float* __restrict__ bih)
{
    extern __shared__ __half smh[];
    const int tid = threadIdx.x;
    const int lane = tid & 31, wid = tid >> 5;
    const int gid = lane >> 2, tig = lane & 3;
    const int wm = (wid >> 2) * 64, wn = (wid & 3) * 32;
    const int n0 = blockIdx.x * 128, m0 = blockIdx.y * 128;  // N fastest -> W L2-resident
    const unsigned sbase = (unsigned)__cvta_generic_to_shared(smh);

    const int arow = (lane < 16) ? lane : (lane - 16);
    const int akoff = (lane >= 16) ? 8 : 0;       // halfs
    const int bnrow = lane & 7, bk8 = (lane >> 3) * 8;

    float c[4][4][4];
    #pragma unroll
    for (int i = 0; i < 4; i++)
        #pragma unroll
        for (int j = 0; j < 4; j++)
            #pragma unroll
            for (int k = 0; k < 4; k++) c[i][j][k] = 0.f;

// stage s: A at s*10240 B, B at 40960 + s*10240 B; rows padded to 40 halfs (80 B)
#define G1_ISSUE(kt) do {                                                        \
        int _s = (kt) & 3;                                                       \
        unsigned _ab = sbase + (unsigned)(_s * 10240);                           \
        unsigned _bb = _ab + 40960u;                                             \
        _Pragma("unroll")                                                        \
        for (int _j = 0; _j < 2; _j++) {                                         \
            int _i = _j * 256 + tid, _r = _i >> 2, _sg = _i & 3;                 \
            unsigned _off = (unsigned)(_r * 80 + _sg * 16);                      \
            const __half* _sa = A + (size_t)(m0 + _r) * Ii + (kt) * 32 + _sg * 8;\
            const __half* _sb = W + (size_t)(n0 + _r) * Ii + (kt) * 32 + _sg * 8;\
            asm volatile("cp.async.cg.shared.global [%0], [%1], 16;"             \
                         :: "r"(_ab + _off), "l"(_sa));                          \
            asm volatile("cp.async.cg.shared.global [%0], [%1], 16;"             \
                         :: "r"(_bb + _off), "l"(_sb));                          \
        }                                                                        \
        asm volatile("cp.async.commit_group;");                                  \
    } while (0)

    G1_ISSUE(0); G1_ISSUE(1); G1_ISSUE(2);

    #pragma unroll 1
    for (int kt = 0; kt < 32; ++kt) {
        if (kt < 30)       asm volatile("cp.async.wait_group 2;");
        else if (kt == 30) asm volatile("cp.async.wait_group 1;");
        else               asm volatile("cp.async.wait_group 0;");
        __syncthreads();
        if (kt + 3 < 32) G1_ISSUE(kt + 3);

        unsigned ab = sbase + (unsigned)((kt & 3) * 10240);
        unsigned bb = ab + 40960u;
        unsigned bf[4][4];
        #pragma unroll
        for (int in = 0; in < 4; in++)
            LDSM4(bf[in], bb + (unsigned)((wn + in * 8 + bnrow) * 80 + bk8 * 2));
        #pragma unroll
        for (int s = 0; s < 2; s++) {
            unsigned a[4][4];
            #pragma unroll
            for (int im = 0; im < 4; im++)
                LDSM4(a[im], ab + (unsigned)((wm + im * 16 + arow) * 80 + (akoff + s * 16) * 2));
            #pragma unroll
            for (int im = 0; im < 4; im++)
                #pragma unroll
                for (int in = 0; in < 4; in++)
                    mma16(c[im][in], a[im], &bf[in][s * 2]);
        }
    }
#undef G1_ISSUE

    // epilogue: +bias, transpose row m=(b*512+t) -> gi row (t*64+b)
    #pragma unroll
    for (int im = 0; im < 4; im++) {
        int mA = m0 + wm + im * 16 + gid;
        int mB = mA + 8;
        int rowA = (mA & 511) * Bb + (mA >> 9);
        int rowB = (mB & 511) * Bb + (mB >> 9);
        #pragma unroll
        for (int in = 0; in < 4; in++) {
            int cn = n0 + wn + in * 8 + tig * 2;
            float bx = bih[cn], by = bih[cn + 1];
            float2 v0 = make_float2(c[im][in][0] + bx, c[im][in][1] + by);
            float2 v1 = make_float2(c[im][in][2] + bx, c[im][in][3] + by);
            *(float2*)&g_gi[(size_t)rowA * G3 + cn] = v0;
            *(float2*)&g_gi[(size_t)rowB * G3 + cn] = v1;
        }
    }
}

// ---------------- persistent recurrent kernel: all 512 steps, fp16 MMA ----------------
// 128 CTAs x 8 h-cols, 8 warps, K-split (warps 0-3: K[0,512), 4-7: K[512,1024)).
// FULL-SLAB mainloop: each warp's smem holds its entire 16x512-half h slab.
// All 32 cp.asyncs issued at step start in 2 K-half commit groups; one
// wait_group 1 -> compute chunks 0-7 straight-line; wait_group 0 -> chunks
// 8-15. No ring, no per-chunk waits. W_hh resident in smem (fp16).
// fp32 accumulate + fp32 gate math; release/acquire grid barrier per step.
__global__ void __launch_bounds__(256, 1) rec_kernel(
    const float* __restrict__ Whh, const float* __restrict__ bhh,
    float* __restrict__ outp)
{
    extern __shared__ __half dynh[];
    __half* wsh = dynh;                          // W_hh: 24 * WSTRH halfs
    __half* hsu = wsh + 24 * WSTRH;              // 8 warps x 16 rows x HROW halfs
    __shared__ float red[128 * 13];              // K-split partials
    __shared__ float bsh[24];

    const int tid = threadIdx.x;
    const int lane = tid & 31, wid = tid >> 5;
    const int gid = lane >> 2, tig = lane & 3;
    const int ks = wid >> 2;                     // K-split group 0/1
    const int mrow0 = (wid & 3) * 16;            // warp's 16 M-rows
    const int col0 = blockIdx.x * 8;
    const int b0r = mrow0 + gid;
    __half* hw = hsu + wid * (16 * HROW);        // this warp's slab
    const unsigned hw_u32 = (unsigned)__cvta_generic_to_shared(hw);
    const unsigned ws_u32 = (unsigned)__cvta_generic_to_shared(wsh);

    // Load W slice once (fp16): row r = (gate r/8, col col0 + r%8), K=1024.
    for (int f = tid; f < 24 * 256; f += 256) {
        int r = f >> 8, cq = f & 255;
        float4 v = *(const float4*)&Whh[(size_t)((r >> 3) * Hh + col0 + (r & 7)) * Hh + cq * 4];
        *(__half2*)&wsh[r * WSTRH + cq * 4]     = __floats2half2_rn(v.x, v.y);
        *(__half2*)&wsh[r * WSTRH + cq * 4 + 2] = __floats2half2_rn(v.z, v.w);
    }
    if (tid < 24) bsh[tid] = bhh[(tid >> 3) * Hh + col0 + (tid & 7)];

    // ldmatrix per-lane addressing (validated fp16 layouts)
    const int arow = (lane < 16) ? lane : (lane - 16);
    const int akoff = (lane >= 16) ? 8 : 0;
    const unsigned a_addr0 = hw_u32 + ((unsigned)(arow * HROW + akoff) << 1);
    const int b_nrow = lane & 7, b_k8 = (lane >> 3) * 8;
    unsigned b_addr[3];
    #pragma unroll
    for (int g = 0; g < 3; g++)
        b_addr[g] = ws_u32 + ((unsigned)((g * 8 + b_nrow) * WSTRH + b_k8) << 1);

    float hloc[4] = {0.f, 0.f, 0.f, 0.f};
    if (wid < 4) {
        int cb = col0 + tig * 2;
        hloc[0] = g_h[0][b0r * Hh + cb];
        hloc[1] = g_h[0][b0r * Hh + cb + 1];
        hloc[2] = g_h[0][(b0r + 8) * Hh + cb];
        hloc[3] = g_h[0][(b0r + 8) * Hh + cb + 1];
    }
    __syncthreads();

    const int kbase = ks * 512;                  // warp group's K offset (halfs)

    // prefetch gi + done-mask for t=0
    float gpre[12], mb0 = 0.f, mb1 = 0.f;
    if (wid < 4) {
        int cb = col0 + tig * 2;
        const float* g0 = g_gi + (size_t)b0r * G3;
        const float* g1 = g_gi + (size_t)(b0r + 8) * G3;
        #pragma unroll
        for (int g = 0; g < 3; g++) {
            float2 p0 = __ldcg((const float2*)(g0 + g * Hh + cb));
            float2 p1 = __ldcg((const float2*)(g1 + g * Hh + cb));
            gpre[g * 2] = p0.x;     gpre[g * 2 + 1] = p0.y;
            gpre[6 + g * 2] = p1.x; gpre[6 + g * 2 + 1] = p1.y;
        }
        mb0 = __ldg(&g_dm[b0r]);
        mb1 = __ldg(&g_dm[b0r + 8]);
    }

    for (int t = 0; t < Tt; ++t) {
        const __half* __restrict__ hh_in  = g_hh[t & 1];
        __half* __restrict__       hh_out = g_hh[(t + 1) & 1];

        // issue entire slab: group A = K-halfs [0,256), group B = [256,512)
        #pragma unroll
        for (int j = 0; j < 16; ++j) {
            int idx = j * 32 + lane, row = idx >> 5, seg = idx & 31;
            unsigned dst = hw_u32 + (unsigned)(row * (HROW * 2) + seg * 16);
            const __half* src = hh_in + (mrow0 + row) * Hh + kbase + seg * 8;
            asm volatile("cp.async.cg.shared.global [%0], [%1], 16;"
                         :: "r"(dst), "l"(src));
        }
        asm volatile("cp.async.commit_group;");
        #pragma unroll
        for (int j = 0; j < 16; ++j) {
            int idx = j * 32 + lane, row = idx >> 5, seg = idx & 31;
            unsigned dst = hw_u32 + (unsigned)(row * (HROW * 2) + 512 + seg * 16);
            const __half* src = hh_in + (mrow0 + row) * Hh + kbase + 256 + seg * 8;
            asm volatile("cp.async.cg.shared.global [%0], [%1], 16;"
                         :: "r"(dst), "l"(src));
        }
        asm volatile("cp.async.commit_group;");

        float c[3][4];
        #pragma unroll
        for (int g = 0; g < 3; g++)
            #pragma unroll
            for (int s = 0; s < 4; s++) c[g][s] = 0.f;

        asm volatile("cp.async.wait_group 1;");
        #pragma unroll
        for (int i = 0; i < 8; ++i) {
            const int kb = kbase + i * 32;       // halfs
            unsigned bf[3][4];
            #pragma unroll
            for (int g = 0; g < 3; g++)
                LDSM4(bf[g], b_addr[g] + ((unsigned)kb << 1));
            #pragma unroll
            for (int s = 0; s < 2; s++) {
                unsigned a[4];
                LDSM4(a, a_addr0 + (unsigned)(i * 64 + s * 32));
                #pragma unroll
                for (int g = 0; g < 3; g++)
                    mma16(c[g], a, &bf[g][s * 2]);
            }
        }
        asm volatile("cp.async.wait_group 0;");
        #pragma unroll
        for (int i = 8; i < 16; ++i) {
            const int kb = kbase + i * 32;
            unsigned bf[3][4];
            #pragma unroll
            for (int g = 0; g < 3; g++)
                LDSM4(bf[g], b_addr[g] + ((unsigned)kb << 1));
            #pragma unroll
            for (int s = 0; s < 2; s++) {
                unsigned a[4];
                LDSM4(a, a_addr0 + (unsigned)(i * 64 + s * 32));
                #pragma unroll
                for (int g = 0; g < 3; g++)
                    mma16(c[g], a, &bf[g][s * 2]);
            }
        }

        // K-split reduction
        if (wid >= 4) {
            int base = (tid - 128) * 13;
            #pragma unroll
            for (int g = 0; g < 3; g++)
                #pragma unroll
                for (int s = 0; s < 4; s++) red[base + g * 4 + s] = c[g][s];
        }
        __syncthreads();

        if (wid < 4) {
            int base = tid * 13;
            float hn[4];
            #pragma unroll
            for (int s = 0; s < 4; s++) {
                int r = s >> 1, i = s & 1;
                int cc = tig * 2 + i;
                float mb = r ? mb1 : mb0;
                float gr = (c[0][s] + red[base + s])     * mb + bsh[cc];
                float gz = (c[1][s] + red[base + 4 + s]) * mb + bsh[8 + cc];
                float gn = (c[2][s] + red[base + 8 + s]) * mb + bsh[16 + cc];
                float rg = __fdividef(1.f, 1.f + __expf(-(gpre[r * 6 + i] + gr)));
                float zg = __fdividef(1.f, 1.f + __expf(-(gpre[r * 6 + 2 + i] + gz)));
                float xa = gpre[r * 6 + 4 + i] + rg * gn;
                float ng = 1.f - __fdividef(2.f, __expf(2.f * xa) + 1.f);
                float hm = hloc[s] * mb;
                hn[s] = (1.f - zg) * ng + zg * hm;
                hloc[s] = hn[s];
            }
            int cb = col0 + tig * 2;
            __half2 p01 = __floats2half2_rn(hn[0], hn[1]);
            __half2 p23 = __floats2half2_rn(hn[2], hn[3]);
            __stcg((unsigned*)&hh_out[b0r * Hh + cb],       *(unsigned*)&p01);
            __stcg((unsigned*)&hh_out[(b0r + 8) * Hh + cb], *(unsigned*)&p23);
            __stcs((float2*)&outp[((size_t)b0r * Tt + t) * Hh + cb],       make_float2(hn[0], hn[1]));
            __stcs((float2*)&outp[((size_t)(b0r + 8) * Tt + t) * Hh + cb], make_float2(hn[2], hn[3]));
            if (t == Tt - 1) {
                *(float2*)&g_h[0][b0r * Hh + cb]       = make_float2(hn[0], hn[1]);
                *(float2*)&g_h[0][(b0r + 8) * Hh + cb] = make_float2(hn[2], hn[3]);
            }
        }

        // prefetch gi + mask for t+1 (independent of h) — hides under the barrier
        if (wid < 4 && t + 1 < Tt) {
            const float* gi_n = g_gi + (size_t)(t + 1) * (Bb * G3);
            int cb = col0 + tig * 2;
            const float* g0 = gi_n + (size_t)b0r * G3;
            const float* g1 = gi_n + (size_t)(b0r + 8) * G3;
            #pragma unroll
            for (int g = 0; g < 3; g++) {
                float2 p0 = __ldcg((const float2*)(g0 + g * Hh + cb));
                float2 p1 = __ldcg((const float2*)(g1 + g * Hh + cb));
                gpre[g * 2] = p0.x;     gpre[g * 2 + 1] = p0.y;
                gpre[6 + g * 2] = p1.x; gpre[6 + g * 2 + 1] = p1.y;
            }
            mb0 = __ldg(&g_dm[(t + 1) * Bb + b0r]);
            mb1 = __ldg(&g_dm[(t + 1) * Bb + b0r + 8]);
        }

        // grid barrier: release/acquire carries the h_out hand-off.
        __syncthreads();
        if (tid == 0) {
            unsigned target = (unsigned)(t + 1) * (unsigned)gridDim.x;
            unsigned one = 1u, v;
            asm volatile("red.release.gpu.global.add.u32 [%0], %1;"
                         :: "l"(&g_bar), "r"(one) : "memory");
            do {
                asm volatile("ld.acquire.gpu.global.u32 %0, [%1];"
                             : "=r"(v) : "l"(&g_bar) : "memory");
            } while (v < target);
        }
        __syncthreads();
    }
}

__global__ void tail_kernel(float* __restrict__ dst) {
    int i = blockIdx.x * blockDim.x + threadIdx.x;
    if (i < Bb * Hh) dst[i] = g_h[0][i];   // final h written by rec at t=511
}

extern "C" void kernel_launch(void* const* d_in, const int* in_sizes, int n_in,
                              void* d_out, int out_size) {
    const float* input  = (const float*)d_in[0];
    const float* hidden = (const float*)d_in[1];
    const void*  done   = d_in[2];
    const float* W_ih   = (const float*)d_in[3];
    const float* W_hh   = (const float*)d_in[4];
    const float* b_ih   = (const float*)d_in[5];
    const float* b_hh   = (const float*)d_in[6];
    float* out = (float*)d_out;

    const int rec_smem   = (24 * WSTRH + 8 * 16 * HROW) * 2;  // 182656 B
    const int gemm1_smem = 81920;                             // 4 stages x (A+B) fp16

    cudaFuncSetAttribute(gemm1_kernel, cudaFuncAttributeMaxDynamicSharedMemorySize, gemm1_smem);
    cudaFuncSetAttribute(rec_kernel, cudaFuncAttributeMaxDynamicSharedMemorySize, rec_smem);

    detect_kernel<<<1, 256>>>((const unsigned*)done);
    prep_kernel<<<256, 256>>>(done, hidden);
    {
        int n8i = (Bb * Tt * Ii) / 8;   // 4194304
        int n8w = (G3 * Ii) / 8;        // 393216
        cvt_kernel<<<(n8i + 255) / 256, 256>>>(input, n8i, 0);
        cvt_kernel<<<(n8w + 255) / 256, 256>>>(W_ih, n8w, 1);
    }
    {
        void* pin = nullptr; void* pw = nullptr;
        cudaGetSymbolAddress(&pin, g_inh);
        cudaGetSymbolAddress(&pw, g_wih);
        gemm1_kernel<<<dim3(G3 / 128, (Bb * Tt) / 128), 256, gemm1_smem>>>(
            (const __half*)pin, (const __half*)pw, b_ih);
    }
    rec_kernel<<<NCTA, 256, rec_smem>>>(W_hh, b_hh, out);
    if (out_size >= Bb * Tt * Hh + Bb * Hh)
        tail_kernel<<<64, 1024>>>(out + (size_t)Bb * Tt * Hh);
}